// round 8
// baseline (speedup 1.0000x reference)
#include <cuda_runtime.h>

#define BB 16
#define TT 12
#define NN 1024
#define EMB 10
#define DIN 21      // 1 + 2*EMB
#define DOUT 64
#define FF 85       // DIN + DOUT
#define KF 170      // CHEB_K * FF
#define OG 128      // 2*DOUT
#define FG 96       // padded spmm-g cols: 85 data + 1 ones + 10 zero pad

// ---------------- device scratch (static, no allocation) ----------------
__device__ float g_cur[BB*TT*NN*DIN];       // 16.5 MB  time-embedded input
__device__ float g_Wg[NN*KF*OG];            // 89 MB    per-node gate weights
__device__ float g_bg[NN*OG];
__device__ float g_Wc[NN*KF*DOUT];          // 44.5 MB  per-node cand weights
__device__ float g_bc[NN*DOUT];
__device__ float g_h[BB*NN*DOUT];           // GRU state
__device__ float g_M[(size_t)BB*NN*NN];     // 64 MB    stable-softmax numerator
__device__ float g_Yg[BB*NN*FG];            // M @ [cur|h|1]
__device__ float g_Yc[BB*NN*DOUT];          // M @ zh
__device__ float g_zh[BB*NN*DOUT];
__device__ float g_r [BB*NN*DOUT];
__device__ float g_seq[BB*TT*NN*DOUT];      // 48 MB    GRU outputs per step

// diagnostics
__device__ unsigned g_flags;
__device__ float    g_fill;

// ---------------- one-time prep kernels ----------------
__global__ void k_embed(const float* __restrict__ x, const float* __restrict__ Wtod,
                        const float* __restrict__ btod, const float* __restrict__ Wdow,
                        const float* __restrict__ bdow) {
    int i = blockIdx.x * blockDim.x + threadIdx.x;      // over B*T*N
    if (i >= BB*TT*NN) return;
    float v   = x[i*3 + 0];
    int   tod = (int)x[i*3 + 1];
    int   dow = (int)x[i*3 + 2];
    float* c = g_cur + (size_t)i * DIN;
    c[0] = v;
    #pragma unroll
    for (int d = 0; d < EMB; d++) c[1 + d]       = Wtod[tod*EMB + d] + btod[d];
    #pragma unroll
    for (int d = 0; d < EMB; d++) c[1 + EMB + d] = Wdow[dow*EMB + d] + bdow[d];
}

// NOTE: device-global outputs are referenced INSIDE device code only.
__global__ void k_wpool_g(const float* __restrict__ E, const float* __restrict__ pool) {
    long i = (long)blockIdx.x * blockDim.x + threadIdx.x;
    if (i >= (long)NN*KF*OG) return;
    int o  = (int)(i % OG);
    int kf = (int)((i / OG) % KF);
    int n  = (int)(i / ((long)OG*KF));
    float s = 0.f;
    #pragma unroll
    for (int d = 0; d < EMB; d++)
        s += E[n*EMB + d] * pool[((long)d*KF + kf)*OG + o];
    g_Wg[i] = s;
}

__global__ void k_wpool_c(const float* __restrict__ E, const float* __restrict__ pool) {
    long i = (long)blockIdx.x * blockDim.x + threadIdx.x;
    if (i >= (long)NN*KF*DOUT) return;
    int o  = (int)(i % DOUT);
    int kf = (int)((i / DOUT) % KF);
    int n  = (int)(i / ((long)DOUT*KF));
    float s = 0.f;
    #pragma unroll
    for (int d = 0; d < EMB; d++)
        s += E[n*EMB + d] * pool[((long)d*KF + kf)*DOUT + o];
    g_Wc[i] = s;
}

__global__ void k_bpool_g(const float* __restrict__ E, const float* __restrict__ bpool) {
    int i = blockIdx.x * blockDim.x + threadIdx.x;
    if (i >= NN*OG) return;
    int o = i % OG, n = i / OG;
    float s = 0.f;
    #pragma unroll
    for (int d = 0; d < EMB; d++) s += E[n*EMB + d] * bpool[d*OG + o];
    g_bg[i] = s;
}

__global__ void k_bpool_c(const float* __restrict__ E, const float* __restrict__ bpool) {
    int i = blockIdx.x * blockDim.x + threadIdx.x;
    if (i >= NN*DOUT) return;
    int o = i % DOUT, n = i / DOUT;
    float s = 0.f;
    #pragma unroll
    for (int d = 0; d < EMB; d++) s += E[n*EMB + d] * bpool[d*DOUT + o];
    g_bc[i] = s;
}

__global__ void k_hinit(const float* __restrict__ init_state) {
    int i = blockIdx.x * blockDim.x + threadIdx.x;
    if (i < BB*NN*DOUT) g_h[i] = init_state[i];
}

// ---------------- per-step kernels ----------------
// Stable: M[b,n,m] = exp(relu(l) - rowmax(relu(l))), l = sum_d E[n,d]E[m,d]e1[d]e2[d]
__global__ void k_adj(int t, const float* __restrict__ E,
                      const float* __restrict__ ne1, const float* __restrict__ ne2) {
    __shared__ float Es[NN*EMB];        // 40 KB: whole embedding table
    __shared__ float Er[16][EMB];
    __shared__ float sred[16][8];
    __shared__ float rowmax[16];
    int b = blockIdx.y, n0 = blockIdx.x * 16, tid = threadIdx.x;

    for (int idx = tid; idx < NN*EMB; idx += 256) Es[idx] = E[idx];
    if (tid < 16*EMB) {
        int i = tid / EMB, d = tid % EMB;
        float s = ne1[(b*TT + t)*EMB + d] * ne2[(b*TT + t)*EMB + d];
        Er[i][d] = E[(n0 + i)*EMB + d] * s;
    }
    __syncthreads();

    float lmax[16];
    #pragma unroll
    for (int r = 0; r < 16; r++) lmax[r] = 0.f;   // relu floor
    for (int c = 0; c < 4; c++) {
        int m = c * 256 + tid;
        float em[EMB];
        #pragma unroll
        for (int d = 0; d < EMB; d++) em[d] = Es[m*EMB + d];
        #pragma unroll
        for (int r = 0; r < 16; r++) {
            float l = 0.f;
            #pragma unroll
            for (int d = 0; d < EMB; d++) l += em[d] * Er[r][d];
            lmax[r] = fmaxf(lmax[r], l);
        }
    }
    int lane = tid & 31, w = tid >> 5;
    #pragma unroll
    for (int r = 0; r < 16; r++) {
        float v = lmax[r];
        #pragma unroll
        for (int off = 16; off; off >>= 1) v = fmaxf(v, __shfl_xor_sync(0xffffffffu, v, off));
        if (lane == 0) sred[r][w] = v;
    }
    __syncthreads();
    if (tid < 16) {
        float v = sred[tid][0];
        #pragma unroll
        for (int w2 = 1; w2 < 8; w2++) v = fmaxf(v, sred[tid][w2]);
        rowmax[tid] = v;
    }
    __syncthreads();

    for (int c = 0; c < 4; c++) {
        int m = c * 256 + tid;
        float em[EMB];
        #pragma unroll
        for (int d = 0; d < EMB; d++) em[d] = Es[m*EMB + d];
        #pragma unroll
        for (int r = 0; r < 16; r++) {
            float l = 0.f;
            #pragma unroll
            for (int d = 0; d < EMB; d++) l += em[d] * Er[r][d];
            l = fmaxf(l, 0.f);
            g_M[((size_t)(b*NN) + (n0 + r))*NN + m] = __expf(l - rowmax[r]);
        }
    }
}

// Yg[b,n,0:96] = M[b] @ [cur_t | h | ones | 0pad]   (col 85 = rowsum)
__global__ void k_spmm_g(int t) {
    __shared__ float As[64][65];
    __shared__ float Xs[64][FG];
    int b = blockIdx.y, n0 = blockIdx.x * 64, tid = threadIdx.x;
    int tx = tid % 16, ty = tid / 16;
    float acc[4][6];
    #pragma unroll
    for (int i = 0; i < 4; i++)
        #pragma unroll
        for (int j = 0; j < 6; j++) acc[i][j] = 0.f;

    const float* curb = g_cur + (size_t)(b*TT + t) * NN * DIN;
    const float* hb   = g_h   + (size_t)b * NN * DOUT;

    for (int mt = 0; mt < 16; mt++) {
        int m0 = mt * 64;
        __syncthreads();
        for (int idx = tid; idx < 64*64; idx += 256) {
            int r = idx >> 6, m = idx & 63;
            As[r][m] = g_M[((size_t)(b*NN) + n0 + r)*NN + m0 + m];
        }
        for (int idx = tid; idx < 64*FG; idx += 256) {
            int mm = idx / FG, f = idx % FG;
            int m = m0 + mm;
            float v;
            if      (f < DIN) v = curb[m*DIN + f];
            else if (f < FF)  v = hb[m*DOUT + (f - DIN)];
            else              v = (f == FF) ? 1.f : 0.f;
            Xs[mm][f] = v;
        }
        __syncthreads();
        #pragma unroll 4
        for (int mm = 0; mm < 64; mm++) {
            float a[4], xv[6];
            #pragma unroll
            for (int i = 0; i < 4; i++) a[i] = As[ty*4 + i][mm];
            #pragma unroll
            for (int j = 0; j < 6; j++) xv[j] = Xs[mm][tx + 16*j];
            #pragma unroll
            for (int i = 0; i < 4; i++)
                #pragma unroll
                for (int j = 0; j < 6; j++) acc[i][j] += a[i] * xv[j];
        }
    }
    #pragma unroll
    for (int i = 0; i < 4; i++)
        #pragma unroll
        for (int j = 0; j < 6; j++)
            g_Yg[((size_t)(b*NN) + n0 + ty*4 + i)*FG + tx + 16*j] = acc[i][j];
}

// Yc[b,n,0:64] = M[b] @ zh
__global__ void k_spmm_c() {
    __shared__ float As[64][65];
    __shared__ float Xs[64][DOUT];
    int b = blockIdx.y, n0 = blockIdx.x * 64, tid = threadIdx.x;
    int tx = tid % 16, ty = tid / 16;
    float acc[4][4];
    #pragma unroll
    for (int i = 0; i < 4; i++)
        #pragma unroll
        for (int j = 0; j < 4; j++) acc[i][j] = 0.f;

    const float* zb = g_zh + (size_t)b * NN * DOUT;
    for (int mt = 0; mt < 16; mt++) {
        int m0 = mt * 64;
        __syncthreads();
        for (int idx = tid; idx < 64*64; idx += 256) {
            int r = idx >> 6, m = idx & 63;
            As[r][m] = g_M[((size_t)(b*NN) + n0 + r)*NN + m0 + m];
        }
        for (int idx = tid; idx < 64*DOUT; idx += 256) {
            int mm = idx >> 6, f = idx & 63;
            Xs[mm][f] = zb[(m0 + mm)*DOUT + f];
        }
        __syncthreads();
        #pragma unroll 4
        for (int mm = 0; mm < 64; mm++) {
            float a[4], xv[4];
            #pragma unroll
            for (int i = 0; i < 4; i++) a[i] = As[ty*4 + i][mm];
            #pragma unroll
            for (int j = 0; j < 4; j++) xv[j] = Xs[mm][tx + 16*j];
            #pragma unroll
            for (int i = 0; i < 4; i++)
                #pragma unroll
                for (int j = 0; j < 4; j++) acc[i][j] += a[i] * xv[j];
        }
    }
    #pragma unroll
    for (int i = 0; i < 4; i++)
        #pragma unroll
        for (int j = 0; j < 4; j++)
            g_Yc[((size_t)(b*NN) + n0 + ty*4 + i)*DOUT + tx + 16*j] = acc[i][j];
}

// gate FC: one CTA per node n, all 16 batches
__global__ void k_fc_g(int t) {
    __shared__ float xs[16][172];
    __shared__ float Ws[10][128];
    int n = blockIdx.x, tid = threadIdx.x;

    for (int idx = tid; idx < 16*KF; idx += 128) {
        int b = idx / KF, f = idx % KF;
        float v;
        if      (f < DIN) v = g_cur[((size_t)(b*TT + t)*NN + n)*DIN + f];
        else if (f < FF)  v = g_h[((size_t)b*NN + n)*DOUT + (f - DIN)];
        else {
            const float* y = g_Yg + ((size_t)b*NN + n)*FG;
            v = y[f - FF] / y[FF];
        }
        xs[b][f] = v;
    }
    __syncthreads();

    int og = tid & 31, bg = tid >> 5;
    float acc[4][4];
    #pragma unroll
    for (int i = 0; i < 4; i++)
        #pragma unroll
        for (int j = 0; j < 4; j++) acc[i][j] = 0.f;

    const float* Wn = g_Wg + (size_t)n * KF * OG;
    for (int fc = 0; fc < KF; fc += 10) {
        __syncthreads();
        for (int idx = tid; idx < 10*128; idx += 128)
            ((float*)Ws)[idx] = Wn[fc*128 + idx];
        __syncthreads();
        #pragma unroll
        for (int ff = 0; ff < 10; ff++) {
            float xv[4], wv[4];
            #pragma unroll
            for (int i = 0; i < 4; i++) xv[i] = xs[bg*4 + i][fc + ff];
            #pragma unroll
            for (int j = 0; j < 4; j++) wv[j] = Ws[ff][og + 32*j];
            #pragma unroll
            for (int i = 0; i < 4; i++)
                #pragma unroll
                for (int j = 0; j < 4; j++) acc[i][j] += xv[i] * wv[j];
        }
    }
    #pragma unroll
    for (int i = 0; i < 4; i++) {
        #pragma unroll
        for (int j = 0; j < 4; j++) {
            int b = bg*4 + i, o = og + 32*j;
            float v  = acc[i][j] + g_bg[n*OG + o];
            float sg = 1.f / (1.f + __expf(-v));
            size_t base = ((size_t)b*NN + n) * DOUT;
            if (o < DOUT) g_zh[base + o] = sg * g_h[base + o];
            else          g_r[base + (o - DOUT)] = sg;
        }
    }
}

// candidate FC + GRU update; writes new h and seq[t]
__global__ void k_fc_c(int t) {
    __shared__ float xs[16][172];
    __shared__ float Ws[10][64];
    int n = blockIdx.x, tid = threadIdx.x;

    for (int idx = tid; idx < 16*KF; idx += 128) {
        int b = idx / KF, f = idx % KF;
        float v;
        if      (f < DIN) v = g_cur[((size_t)(b*TT + t)*NN + n)*DIN + f];
        else if (f < FF)  v = g_zh[((size_t)b*NN + n)*DOUT + (f - DIN)];
        else {
            int fp = f - FF;
            float num = (fp < DIN) ? g_Yg[((size_t)b*NN + n)*FG + fp]
                                   : g_Yc[((size_t)b*NN + n)*DOUT + (fp - DIN)];
            v = num / g_Yg[((size_t)b*NN + n)*FG + FF];
        }
        xs[b][f] = v;
    }
    __syncthreads();

    int og = tid & 31, bg = tid >> 5;
    float acc[4][2];
    #pragma unroll
    for (int i = 0; i < 4; i++) { acc[i][0] = 0.f; acc[i][1] = 0.f; }

    const float* Wn = g_Wc + (size_t)n * KF * DOUT;
    for (int fc = 0; fc < KF; fc += 10) {
        __syncthreads();
        for (int idx = tid; idx < 10*64; idx += 128)
            ((float*)Ws)[idx] = Wn[fc*64 + idx];
        __syncthreads();
        #pragma unroll
        for (int ff = 0; ff < 10; ff++) {
            float xv[4], wv[2];
            #pragma unroll
            for (int i = 0; i < 4; i++) xv[i] = xs[bg*4 + i][fc + ff];
            wv[0] = Ws[ff][og]; wv[1] = Ws[ff][og + 32];
            #pragma unroll
            for (int i = 0; i < 4; i++) {
                acc[i][0] += xv[i] * wv[0];
                acc[i][1] += xv[i] * wv[1];
            }
        }
    }
    #pragma unroll
    for (int i = 0; i < 4; i++) {
        #pragma unroll
        for (int j = 0; j < 2; j++) {
            int b = bg*4 + i, o = og + 32*j;
            float hc = tanhf(acc[i][j] + g_bc[n*DOUT + o]);
            size_t base = ((size_t)b*NN + n) * DOUT;
            float r    = g_r[base + o];
            float hold = g_h[base + o];
            float hn   = r * hold + (1.f - r) * hc;
            g_h[base + o] = hn;
            g_seq[((size_t)(b*TT + t)*NN + n)*DOUT + o] = hn;
        }
    }
}

// ---------------- temporal attention ----------------
__global__ void k_attn(const float* __restrict__ WQ, const float* __restrict__ bQ,
                       const float* __restrict__ WK, const float* __restrict__ bK,
                       const float* __restrict__ WV, const float* __restrict__ bV,
                       float* __restrict__ out) {
    __shared__ float xsm[2*TT*65];
    __shared__ float Qs [2*TT*65];
    __shared__ float Ks [2*TT*65];
    __shared__ float Vs [2*TT*65];
    __shared__ float P  [2*TT*TT];

    int b = blockIdx.y, n0 = blockIdx.x * 2;
    int tid = threadIdx.x, ng = tid >> 6, o = tid & 63, n = n0 + ng;

    #pragma unroll
    for (int t = 0; t < TT; t++)
        xsm[(ng*TT + t)*65 + o] = g_seq[((size_t)(b*TT + t)*NN + n)*DOUT + o];
    __syncthreads();

    float q[TT], k[TT], v[TT];
    {
        float bq = __ldg(bQ + o), bk = __ldg(bK + o), bv = __ldg(bV + o);
        #pragma unroll
        for (int t = 0; t < TT; t++) { q[t] = bq; k[t] = bk; v[t] = bv; }
    }
    for (int f = 0; f < 64; f++) {
        float wq = __ldg(WQ + f*64 + o);
        float wk = __ldg(WK + f*64 + o);
        float wv = __ldg(WV + f*64 + o);
        #pragma unroll
        for (int t = 0; t < TT; t++) {
            float xv = xsm[(ng*TT + t)*65 + f];
            q[t] += xv * wq; k[t] += xv * wk; v[t] += xv * wv;
        }
    }
    #pragma unroll
    for (int t = 0; t < TT; t++) {
        Qs[(ng*TT + t)*65 + o] = q[t];
        Ks[(ng*TT + t)*65 + o] = k[t];
        Vs[(ng*TT + t)*65 + o] = v[t];
    }
    __syncthreads();

    for (int p = o; p < TT*TT; p += 64) {
        int t1 = p / TT, s1 = p % TT;
        float s = 0.f;
        #pragma unroll
        for (int f = 0; f < 64; f++)
            s += Qs[(ng*TT + t1)*65 + f] * Ks[(ng*TT + s1)*65 + f];
        P[(ng*TT + t1)*TT + s1] = s * 0.125f;
    }
    __syncthreads();

    if (tid < 2*TT) {
        int ng2 = tid / TT, t1 = tid % TT;
        float* row = P + (ng2*TT + t1)*TT;
        float m = row[0];
        #pragma unroll
        for (int s = 1; s < TT; s++) m = fmaxf(m, row[s]);
        float sum = 0.f;
        #pragma unroll
        for (int s = 0; s < TT; s++) { float e = __expf(row[s] - m); row[s] = e; sum += e; }
        float inv = 1.f / sum;
        #pragma unroll
        for (int s = 0; s < TT; s++) row[s] *= inv;
    }
    __syncthreads();

    #pragma unroll
    for (int t1 = 0; t1 < TT; t1++) {
        float z = 0.f;
        #pragma unroll
        for (int s1 = 0; s1 < TT; s1++)
            z += P[(ng*TT + t1)*TT + s1] * Vs[(ng*TT + s1)*65 + o];
        out[((size_t)(b*TT + t1)*NN + n)*DOUT + o] = z;
    }
}

__global__ void k_hlast(float* __restrict__ out) {
    int i = blockIdx.x * blockDim.x + threadIdx.x;
    if (i < BB*NN*DOUT) out[(size_t)BB*TT*NN*DOUT + i] = g_h[i];
}

// ---------------- diagnostics (tripwire; removed after first PASS) ----------------
__global__ void k_flag0() { g_flags = 0u; g_fill = 0.f; }

__global__ void k_scan(int which, long n) {
    __shared__ int any;
    if (threadIdx.x == 0) any = 0;
    __syncthreads();
    const float* p;
    switch (which) {
        case 0: p = g_cur; break;
        case 1: p = g_Wc;  break;
        case 2: p = g_bc;  break;
        case 3: p = g_M;   break;
        case 4: p = g_Yg;  break;
        case 5: p = g_zh;  break;
        default: p = g_seq; break;
    }
    long i = (long)blockIdx.x * blockDim.x + threadIdx.x;
    long s = (long)gridDim.x * blockDim.x;
    int loc = 0;
    for (; i < n; i += s) { if (p[i] != 0.f) { loc = 1; break; } }
    if (loc) atomicOr(&any, 1);
    __syncthreads();
    if (threadIdx.x == 0 && any) atomicOr(&g_flags, 1u << which);
}

__global__ void k_verdict() {
    unsigned f = g_flags;
    float fill = 0.f;
    if      (!(f & 1u))  fill = 1e6f;
    else if (!(f & 2u))  fill = 1e9f;
    else if (!(f & 4u))  fill = 1e12f;
    else if (!(f & 8u))  fill = 1e15f;
    else if (!(f & 16u)) fill = 1e18f;
    else if (!(f & 32u)) fill = 1e21f;
    else if (!(f & 64u)) fill = 1e24f;
    g_fill = fill;
}

__global__ void k_fill(float* __restrict__ out, long n) {
    float v = g_fill;
    if (v == 0.f) return;
    long i = (long)blockIdx.x * blockDim.x + threadIdx.x;
    long s = (long)gridDim.x * blockDim.x;
    for (; i < n; i += s) out[i] = v;
}

// ---------------- launch ----------------
extern "C" void kernel_launch(void* const* d_in, const int* in_sizes, int n_in,
                              void* d_out, int out_size) {
    // Resolve inputs by element count (order-invariant for distinct sizes).
    const int esz[19] = {589824, 1048576, 1920, 1920, 10240, 480, 10, 70, 10,
                         4096, 64, 4096, 64, 4096, 64, 217600, 1280, 108800, 640};
    const float* p[19];
    int used[64];
    for (int i = 0; i < 64; i++) used[i] = 0;
    for (int j = 0; j < 19; j++) {
        p[j] = (j < n_in) ? (const float*)d_in[j] : (const float*)d_in[0];
        for (int i = 0; i < n_in && i < 64; i++) {
            if (!used[i] && in_sizes[i] == esz[j]) { p[j] = (const float*)d_in[i]; used[i] = 1; break; }
        }
    }
    const float* x          = p[0];
    const float* init_state = p[1];
    const float* ne_tod     = p[2];
    const float* ne_dow     = p[3];
    const float* node_emb   = p[4];
    const float* Wtod       = p[5];
    const float* btod       = p[6];
    const float* Wdow       = p[7];
    const float* bdow       = p[8];
    const float* WQ         = p[9];
    const float* bQ         = p[10];
    const float* WK         = p[11];
    const float* bK         = p[12];
    const float* WV         = p[13];
    const float* bV         = p[14];
    const float* Wpool_g    = p[15];
    const float* bpool_g    = p[16];
    const float* Wpool_c    = p[17];
    const float* bpool_c    = p[18];
    float* out = (float*)d_out;
    const long OUT0 = (long)BB*TT*NN*DOUT;

    k_flag0<<<1, 1>>>();

    // prep (globals written from device code only — no host-passed symbols!)
    k_embed<<<(BB*TT*NN + 255)/256, 256>>>(x, Wtod, btod, Wdow, bdow);
    k_wpool_g<<<(int)(((long)NN*KF*OG   + 255)/256), 256>>>(node_emb, Wpool_g);
    k_wpool_c<<<(int)(((long)NN*KF*DOUT + 255)/256), 256>>>(node_emb, Wpool_c);
    k_bpool_g<<<(NN*OG   + 255)/256, 256>>>(node_emb, bpool_g);
    k_bpool_c<<<(NN*DOUT + 255)/256, 256>>>(node_emb, bpool_c);
    k_hinit<<<(BB*NN*DOUT + 255)/256, 256>>>(init_state);

    // recurrence
    for (int t = 0; t < TT; t++) {
        k_adj   <<<dim3(NN/16, BB), 256>>>(t, node_emb, ne_tod, ne_dow);
        k_spmm_g<<<dim3(NN/64, BB), 256>>>(t);
        k_fc_g  <<<NN, 128>>>(t);
        k_spmm_c<<<dim3(NN/64, BB), 256>>>();
        k_fc_c  <<<NN, 128>>>(t);
    }

    // attention + h_last
    k_attn<<<dim3(NN/2, BB), 128>>>(WQ, bQ, WK, bK, WV, bV, out);
    if (out_size >= BB*TT*NN*DOUT + BB*NN*DOUT)
        k_hlast<<<(BB*NN*DOUT + 255)/256, 256>>>(out);

    // tripwire diagnostics (first-dead stage -> decade-coded fill)
    k_scan<<<1024, 256>>>(0, (long)BB*TT*NN*DIN);
    k_scan<<<1024, 256>>>(1, (long)NN*KF*DOUT);
    k_scan<<<1024, 256>>>(2, (long)NN*DOUT);
    k_scan<<<1024, 256>>>(3, (long)BB*NN*NN);
    k_scan<<<1024, 256>>>(4, (long)BB*NN*FG);
    k_scan<<<1024, 256>>>(5, (long)BB*NN*DOUT);
    k_scan<<<1024, 256>>>(6, (long)BB*TT*NN*DOUT);
    k_verdict<<<1, 1>>>();
    k_fill<<<2048, 256>>>(out, OUT0);
}